// round 12
// baseline (speedup 1.0000x reference)
#include <cuda_runtime.h>

// LearnableDemosaick: per-pixel soft filter selection over K=8 5x5 filters.
// B=16, H=W=512. Only non-green (checkerboard) pixels need the conv+softmax;
// green pixels copy the mosaic. Packed f32x2 FMA doubles fp32 throughput.
// R7: filters in __constant__ bank. R10: 2 conv px/thread @ 256 thr.
// R11: warp-uniform parity branch -> two static conv paths; pixel rows read
// as 2x LDS.128 (conflict-free) instead of 7x conflicted LDS.32.

#define Bn 16
#define Hd 512
#define Wd 512
#define TW 128   // output cols per block
#define TH 8     // output rows per block
#define NT 256   // threads per block (32 x-segments x 8 rows)

struct QPair { unsigned long long s, g; };  // {s,s} and {g,g} packed f32x2

__constant__ QPair c_quad[200];
__device__   QPair g_stage[200];

__global__ void prep_filters(const float* __restrict__ selF,
                             const float* __restrict__ grnF) {
    int i = threadIdx.x;
    if (i < 200) {
        float s = selF[i], g = grnF[i];
        unsigned long long ss, gg;
        asm("mov.b64 %0, {%1, %1};" : "=l"(ss) : "f"(s));
        asm("mov.b64 %0, {%1, %1};" : "=l"(gg) : "f"(g));
        g_stage[i].s = ss;
        g_stage[i].g = gg;
    }
}

__device__ __forceinline__ unsigned long long ffma2(unsigned long long a,
                                                    unsigned long long b,
                                                    unsigned long long c) {
    unsigned long long d;
    asm("fma.rn.f32x2 %0, %1, %2, %3;" : "=l"(d) : "l"(a), "l"(b), "l"(c));
    return d;
}
__device__ __forceinline__ unsigned long long pk2(float lo, float hi) {
    unsigned long long r;
    asm("mov.b64 %0, {%1, %2};" : "=l"(r) : "f"(lo), "f"(hi));
    return r;
}
__device__ __forceinline__ void upk2(unsigned long long v, float& lo, float& hi) {
    asm("mov.b64 {%0, %1}, %2;" : "=f"(lo), "=f"(hi) : "l"(v));
}

__device__ __forceinline__ float softmax_combine(const float* s, const float* g) {
    float m = s[0];
    #pragma unroll
    for (int k = 1; k < 8; k++) m = fmaxf(m, s[k]);
    float den = 0.f, num = 0.f;
    #pragma unroll
    for (int k = 0; k < 8; k++) {
        float e = __expf(s[k] - m);
        den += e;
        num = fmaf(e, g[k], num);
    }
    return __fdividef(num, den);
}

// Conv path with compile-time parity P0. Pixel pair = tile cols
// (txs+P0+2, txs+P0+4) in output coords; taps span tile cols txs+P0..txs+P0+6.
// f[i] = tile[row][txs+i], i=0..7 from two aligned LDS.128.
// Greens (row parity) are tile cols txs+(1-P0)+2j+2 -> f[(1-P0)+2j+2].
template <int P0>
__device__ __forceinline__ void conv_path(const float (*tile)[TW + 4],
                                          int ty, int txs,
                                          unsigned long long* sA,
                                          unsigned long long* gA,
                                          float* gr) {
    #pragma unroll
    for (int dy = 0; dy < 5; dy++) {
        const float4* vp = reinterpret_cast<const float4*>(&tile[ty + dy][txs]);
        float4 va = vp[0];
        float4 vb = vp[1];
        float f[8] = {va.x, va.y, va.z, va.w, vb.x, vb.y, vb.z, vb.w};

        if (dy == 2) {
            #pragma unroll
            for (int j = 0; j < 2; j++) gr[j] = f[(1 - P0) + 2 * j + 2];
        }

        #pragma unroll
        for (int d = 0; d < 5; d++) {
            const unsigned long long a = pk2(f[d + P0], f[d + P0 + 2]);
            #pragma unroll
            for (int k = 0; k < 8; k++) {
                const QPair fq = c_quad[(dy * 5 + d) * 8 + k];  // const bank, uniform
                sA[k] = ffma2(a, fq.s, sA[k]);
                gA[k] = ffma2(a, fq.g, gA[k]);
            }
        }
    }
}

__global__ void __launch_bounds__(NT)
demosaick_kernel(const float* __restrict__ mosaick,
                 float* __restrict__ out) {
    __shared__ __align__(16) float tile[TH + 4][TW + 4];   // 12 x 132 (row=528B)

    const int tid = threadIdx.x;
    const int x0 = blockIdx.x * TW;
    const int y0 = blockIdx.y * TH;
    const size_t base = (size_t)blockIdx.z * Hd * Wd;

    // Input tile with edge clamp (Halide clamp semantics). Flattened: 1584 elems.
    for (int i = tid; i < (TH + 4) * (TW + 4); i += NT) {
        int r = i / (TW + 4);
        int c = i - r * (TW + 4);
        int gy = y0 + r - 2;
        gy = gy < 0 ? 0 : (gy > Hd - 1 ? Hd - 1 : gy);
        int gx = x0 + c - 2;
        gx = gx < 0 ? 0 : (gx > Wd - 1 ? Wd - 1 : gx);
        tile[r][c] = mosaick[base + (size_t)gy * Wd + gx];
    }
    __syncthreads();

    const int ty  = tid >> 5;         // row within tile (0..7); warp-uniform
    const int txs = (tid & 31) * 4;   // output col base within tile (4-wide)
    const int y   = y0 + ty;          // global row
    const int p0  = (y + 1) & 1;      // non-green column parity; warp-uniform

    unsigned long long sA[8], gA[8];
    #pragma unroll
    for (int k = 0; k < 8; k++) { sA[k] = 0ull; gA[k] = 0ull; }
    float gr[2];

    if (p0 == 0) conv_path<0>(tile, ty, txs, sA, gA, gr);
    else         conv_path<1>(tile, ty, txs, sA, gA, gr);

    // Epilogue: softmax-combine the 2 conv pixels.
    float cv[2];
    {
        float s0[8], s1[8], g0[8], g1[8];
        #pragma unroll
        for (int k = 0; k < 8; k++) { upk2(sA[k], s0[k], s1[k]); upk2(gA[k], g0[k], g1[k]); }
        cv[0] = softmax_combine(s0, g0);
        cv[1] = softmax_combine(s1, g1);
    }

    // Interleave per parity (p0 warp-uniform; selects are cheap and few).
    float o[4];
    #pragma unroll
    for (int j = 0; j < 2; j++) {
        o[2 * j]     = p0 ? gr[j] : cv[j];
        o[2 * j + 1] = p0 ? cv[j] : gr[j];
    }

    *reinterpret_cast<float4*>(out + base + (size_t)y * Wd + x0 + txs) =
        make_float4(o[0], o[1], o[2], o[3]);
}

extern "C" void kernel_launch(void* const* d_in, const int* in_sizes, int n_in,
                              void* d_out, int out_size) {
    const float* mosaick = (const float*)d_in[0];   // [16,1,512,512]
    const float* selF    = (const float*)d_in[1];   // [5,5,8]
    const float* grnF    = (const float*)d_in[2];   // [5,5,8]
    float* out           = (float*)d_out;           // [16,1,512,512]

    prep_filters<<<1, 256>>>(selF, grnF);

    void *dst = nullptr, *src = nullptr;
    cudaGetSymbolAddress(&dst, c_quad);
    cudaGetSymbolAddress(&src, g_stage);
    cudaMemcpyAsync(dst, src, 200 * sizeof(QPair), cudaMemcpyDeviceToDevice);

    dim3 grid(Wd / TW, Hd / TH, Bn);                // (4, 64, 16)
    demosaick_kernel<<<grid, NT>>>(mosaick, out);
}

// round 13
// speedup vs baseline: 1.0942x; 1.0942x over previous
#include <cuda_runtime.h>

// LearnableDemosaick: per-pixel soft filter selection over K=8 5x5 filters.
// B=16, H=W=512. Only non-green (checkerboard) pixels need the conv+softmax;
// green pixels copy the mosaic. Packed f32x2 FMA doubles fp32 throughput.
// R7: filters in __constant__ bank. R10: 2 conv px/thread @ 256 thr.
// R11: warp-uniform parity branch; pixel rows via 2x conflict-free LDS.128.
// R12: __launch_bounds__(256,5) — keep 5 blocks/SM (R11's 54 regs fell to
// 4 blocks and lost the occupancy the LDS fix should have banked).

#define Bn 16
#define Hd 512
#define Wd 512
#define TW 128   // output cols per block
#define TH 8     // output rows per block
#define NT 256   // threads per block (32 x-segments x 8 rows)

struct QPair { unsigned long long s, g; };  // {s,s} and {g,g} packed f32x2

__constant__ QPair c_quad[200];
__device__   QPair g_stage[200];

__global__ void prep_filters(const float* __restrict__ selF,
                             const float* __restrict__ grnF) {
    int i = threadIdx.x;
    if (i < 200) {
        float s = selF[i], g = grnF[i];
        unsigned long long ss, gg;
        asm("mov.b64 %0, {%1, %1};" : "=l"(ss) : "f"(s));
        asm("mov.b64 %0, {%1, %1};" : "=l"(gg) : "f"(g));
        g_stage[i].s = ss;
        g_stage[i].g = gg;
    }
}

__device__ __forceinline__ unsigned long long ffma2(unsigned long long a,
                                                    unsigned long long b,
                                                    unsigned long long c) {
    unsigned long long d;
    asm("fma.rn.f32x2 %0, %1, %2, %3;" : "=l"(d) : "l"(a), "l"(b), "l"(c));
    return d;
}
__device__ __forceinline__ unsigned long long pk2(float lo, float hi) {
    unsigned long long r;
    asm("mov.b64 %0, {%1, %2};" : "=l"(r) : "f"(lo), "f"(hi));
    return r;
}
__device__ __forceinline__ void upk2(unsigned long long v, float& lo, float& hi) {
    asm("mov.b64 {%0, %1}, %2;" : "=f"(lo), "=f"(hi) : "l"(v));
}

__device__ __forceinline__ float softmax_combine(const float* s, const float* g) {
    float m = s[0];
    #pragma unroll
    for (int k = 1; k < 8; k++) m = fmaxf(m, s[k]);
    float den = 0.f, num = 0.f;
    #pragma unroll
    for (int k = 0; k < 8; k++) {
        float e = __expf(s[k] - m);
        den += e;
        num = fmaf(e, g[k], num);
    }
    return __fdividef(num, den);
}

// Conv path with compile-time parity P0. Pixel pair = output cols
// (txs+P0, txs+P0+2); tile col of a pixel is (x-x0)+2, so taps span tile
// cols txs+P0..txs+P0+6. f[i] = tile[row][txs+i] from two aligned LDS.128.
// Greens are output cols txs+(1-P0)+2j -> tile col txs+(1-P0)+2j+2.
template <int P0>
__device__ __forceinline__ void conv_path(const float (*tile)[TW + 4],
                                          int ty, int txs,
                                          unsigned long long* sA,
                                          unsigned long long* gA,
                                          float* gr) {
    #pragma unroll
    for (int dy = 0; dy < 5; dy++) {
        const float4* vp = reinterpret_cast<const float4*>(&tile[ty + dy][txs]);
        float4 va = vp[0];
        float4 vb = vp[1];
        float f[8] = {va.x, va.y, va.z, va.w, vb.x, vb.y, vb.z, vb.w};

        if (dy == 2) {
            #pragma unroll
            for (int j = 0; j < 2; j++) gr[j] = f[(1 - P0) + 2 * j + 2];
        }

        #pragma unroll
        for (int d = 0; d < 5; d++) {
            const unsigned long long a = pk2(f[d + P0], f[d + P0 + 2]);
            #pragma unroll
            for (int k = 0; k < 8; k++) {
                const QPair fq = c_quad[(dy * 5 + d) * 8 + k];  // const bank, uniform
                sA[k] = ffma2(a, fq.s, sA[k]);
                gA[k] = ffma2(a, fq.g, gA[k]);
            }
        }
    }
}

__global__ void __launch_bounds__(NT, 5)
demosaick_kernel(const float* __restrict__ mosaick,
                 float* __restrict__ out) {
    __shared__ __align__(16) float tile[TH + 4][TW + 4];   // 12 x 132 (row=528B)

    const int tid = threadIdx.x;
    const int x0 = blockIdx.x * TW;
    const int y0 = blockIdx.y * TH;
    const size_t base = (size_t)blockIdx.z * Hd * Wd;

    // Input tile with edge clamp (Halide clamp semantics). Flattened: 1584 elems.
    for (int i = tid; i < (TH + 4) * (TW + 4); i += NT) {
        int r = i / (TW + 4);
        int c = i - r * (TW + 4);
        int gy = y0 + r - 2;
        gy = gy < 0 ? 0 : (gy > Hd - 1 ? Hd - 1 : gy);
        int gx = x0 + c - 2;
        gx = gx < 0 ? 0 : (gx > Wd - 1 ? Wd - 1 : gx);
        tile[r][c] = mosaick[base + (size_t)gy * Wd + gx];
    }
    __syncthreads();

    const int ty  = tid >> 5;         // row within tile (0..7); warp-uniform
    const int txs = (tid & 31) * 4;   // output col base within tile (4-wide)
    const int y   = y0 + ty;          // global row
    const int p0  = (y + 1) & 1;      // non-green column parity; warp-uniform

    unsigned long long sA[8], gA[8];
    #pragma unroll
    for (int k = 0; k < 8; k++) { sA[k] = 0ull; gA[k] = 0ull; }
    float gr[2];

    if (p0 == 0) conv_path<0>(tile, ty, txs, sA, gA, gr);
    else         conv_path<1>(tile, ty, txs, sA, gA, gr);

    // Epilogue: softmax-combine the 2 conv pixels.
    float cv[2];
    {
        float s0[8], s1[8], g0[8], g1[8];
        #pragma unroll
        for (int k = 0; k < 8; k++) { upk2(sA[k], s0[k], s1[k]); upk2(gA[k], g0[k], g1[k]); }
        cv[0] = softmax_combine(s0, g0);
        cv[1] = softmax_combine(s1, g1);
    }

    // Interleave per parity (p0 warp-uniform; selects are cheap and few).
    float o[4];
    #pragma unroll
    for (int j = 0; j < 2; j++) {
        o[2 * j]     = p0 ? gr[j] : cv[j];
        o[2 * j + 1] = p0 ? cv[j] : gr[j];
    }

    *reinterpret_cast<float4*>(out + base + (size_t)y * Wd + x0 + txs) =
        make_float4(o[0], o[1], o[2], o[3]);
}

extern "C" void kernel_launch(void* const* d_in, const int* in_sizes, int n_in,
                              void* d_out, int out_size) {
    const float* mosaick = (const float*)d_in[0];   // [16,1,512,512]
    const float* selF    = (const float*)d_in[1];   // [5,5,8]
    const float* grnF    = (const float*)d_in[2];   // [5,5,8]
    float* out           = (float*)d_out;           // [16,1,512,512]

    prep_filters<<<1, 256>>>(selF, grnF);

    void *dst = nullptr, *src = nullptr;
    cudaGetSymbolAddress(&dst, c_quad);
    cudaGetSymbolAddress(&src, g_stage);
    cudaMemcpyAsync(dst, src, 200 * sizeof(QPair), cudaMemcpyDeviceToDevice);

    dim3 grid(Wd / TW, Hd / TH, Bn);                // (4, 64, 16)
    demosaick_kernel<<<grid, NT>>>(mosaick, out);
}